// round 3
// baseline (speedup 1.0000x reference)
#include <cuda_runtime.h>
#include <math.h>

#define N_NODES 100000
#define N_EDGES 3200000
#define TOT_SLOTS (N_EDGES + N_NODES)
#define SCAN_BLOCK 1024
#define SCAN_NBLK ((N_NODES + SCAN_BLOCK - 1) / SCAN_BLOCK)   // 98

// Scratch (device globals zero-initialized at module load; g_deg==0 is the
// entry invariant, re-established by scan1 every run).
// g_xall: 128B record per node, [level 0..3][c 0..7] -> one L1 line per node.
__device__ float4 g_xall[(size_t)N_NODES * 8];
__device__ float  g_dinv[N_NODES];
__device__ int    g_deg[N_NODES];
__device__ int    g_off[N_NODES + 1];
__device__ int    g_cursor[N_NODES];
__device__ int2   g_csr[TOT_SLOTS];     // {src, __float_as_int(dinv[src])}
__device__ int    g_bsum[SCAN_NBLK];

// ---------------- CSR build ----------------

__global__ void count_kernel(const int* __restrict__ dst) {
    int e = blockIdx.x * blockDim.x + threadIdx.x;
    if (e < N_EDGES) atomicAdd(&g_deg[dst[e]], 1);
}

// reads deg (+1 self loop), computes dinv, re-zeroes deg, block-exclusive scan
__global__ void scan1_kernel() {
    __shared__ int sh[SCAN_BLOCK];
    int i = blockIdx.x * SCAN_BLOCK + threadIdx.x;
    int v = 0;
    if (i < N_NODES) {
        v = g_deg[i] + 1;                 // +1 self loop
        g_dinv[i] = rsqrtf((float)v);
        g_deg[i] = 0;                     // restore entry invariant
    }
    sh[threadIdx.x] = v;
    __syncthreads();
    #pragma unroll
    for (int o = 1; o < SCAN_BLOCK; o <<= 1) {
        int t = 0;
        if ((int)threadIdx.x >= o) t = sh[threadIdx.x - o];
        __syncthreads();
        sh[threadIdx.x] += t;
        __syncthreads();
    }
    if (i < N_NODES) g_off[i] = sh[threadIdx.x] - v;  // exclusive, per-block
    if (threadIdx.x == SCAN_BLOCK - 1) g_bsum[blockIdx.x] = sh[SCAN_BLOCK - 1];
}

__global__ void scan2_kernel() {    // one block, 128 threads, Hillis-Steele
    __shared__ int sh[128];
    int t = threadIdx.x;
    int v = (t < SCAN_NBLK) ? g_bsum[t] : 0;
    sh[t] = v;
    __syncthreads();
    #pragma unroll
    for (int o = 1; o < 128; o <<= 1) {
        int x = 0;
        if (t >= o) x = sh[t - o];
        __syncthreads();
        sh[t] += x;
        __syncthreads();
    }
    if (t < SCAN_NBLK) g_bsum[t] = sh[t] - v;   // exclusive across blocks
}

// scan fixup + self-loop CSR entry + cursor init + input MLP, all node-parallel
__global__ void scan3_fill_mlp_kernel(const float* __restrict__ x,
                                      const int* __restrict__ node_index,
                                      const float* __restrict__ emb,
                                      const float* __restrict__ W1,
                                      const float* __restrict__ b1) {
    __shared__ float sW[24 * 8 + 8];
    int t = threadIdx.x;
    if (t < 192) sW[t] = W1[t];
    else if (t < 200) sW[t] = b1[t - 192];
    __syncthreads();

    int i = blockIdx.x * SCAN_BLOCK + t;
    if (i == 0) g_off[N_NODES] = TOT_SLOTS;
    if (i >= N_NODES) return;

    int off = g_off[i] + g_bsum[blockIdx.x];
    g_off[i] = off;
    g_csr[off] = make_int2(i, __float_as_int(g_dinv[i]));
    g_cursor[i] = off + 1;

    // h0 = relu([emb|x] @ W1 + b1)
    float in[24];
    int idx = node_index[i];
    #pragma unroll
    for (int j = 0; j < 8; j++) in[j] = emb[(size_t)idx * 8 + j];
    #pragma unroll
    for (int j = 0; j < 16; j++) in[8 + j] = x[(size_t)i * 16 + j];
    float o[8];
    #pragma unroll
    for (int c = 0; c < 8; c++) {
        float s = sW[192 + c];
        #pragma unroll
        for (int j = 0; j < 24; j++) s = fmaf(in[j], sW[j * 8 + c], s);
        o[c] = fmaxf(s, 0.0f);
    }
    float4* outp = g_xall + (size_t)i * 8;
    outp[0] = make_float4(o[0], o[1], o[2], o[3]);
    outp[1] = make_float4(o[4], o[5], o[6], o[7]);
}

__global__ void fill_edges_kernel(const int* __restrict__ src, const int* __restrict__ dst) {
    int e = blockIdx.x * blockDim.x + threadIdx.x;
    if (e < N_EDGES) {
        int s = src[e];
        int d = dst[e];
        int p = atomicAdd(&g_cursor[d], 1);
        g_csr[p] = make_int2(s, __float_as_int(g_dinv[s]));
    }
}

// ---------------- DNA conv layer: warp per node, batched staged gathers ----

template <int L>
__global__ void __launch_bounds__(256) conv_kernel(
    const float* __restrict__ Wq, const float* __restrict__ Bq,
    const float* __restrict__ Wk, const float* __restrict__ Bk,
    const float* __restrict__ Wv, const float* __restrict__ Bv)
{
    constexpr int CH = 2 * L;       // 16B chunks per edge (8L floats)
    constexpr int S  = 8 * L + 4;   // smem floats per edge (pad kills conflicts)
    __shared__ float sx[8 * 32 * S];

    int warp = threadIdx.x >> 5, lane = threadIdx.x & 31;
    int n = blockIdx.x * 8 + warp;
    if (n >= N_NODES) return;       // warp-uniform exit
    float* ws = sx + warp * (32 * S);

    float wv[8], bv[8];
    #pragma unroll
    for (int c = 0; c < 8; c++) { wv[c] = __ldg(Wv + c); bv[c] = __ldg(Bv + c); }

    float qk[8];
    float qb0 = 0.0f, qb1 = 0.0f;
    if (L > 1) {
        const float* xn = ((const float*)(g_xall + (size_t)n * 8)) + (L - 1) * 8;
        #pragma unroll
        for (int c = 0; c < 8; c++) {
            float q = fmaf(xn[c], __ldg(Wq + c), __ldg(Bq + c));
            qk[c] = 0.5f * q * __ldg(Wk + c);                 // fold 1/sqrt(d)=0.5
            float qb = 0.5f * q * __ldg(Bk + c);
            if (c < 4) qb0 += qb; else qb1 += qb;
        }
    }

    // per-lane chunk mapping, constant across tiles
    int e_[CH], c_[CH];
    #pragma unroll
    for (int r = 0; r < CH; r++) {
        int idx = r * 32 + lane;
        e_[r] = idx / CH;
        c_[r] = idx - e_[r] * CH;
    }

    float dn = g_dinv[n];
    int beg = g_off[n], end = g_off[n + 1];
    float acc[8] = {0.f, 0.f, 0.f, 0.f, 0.f, 0.f, 0.f, 0.f};

    for (int tb = beg; tb < end; tb += 32) {
        int cnt = min(32, end - tb);
        int2 ent = make_int2(0, 0);
        if (lane < cnt) ent = __ldg(&g_csr[tb + lane]);

        // batched cooperative gather: all shfls, then all independent LDG.128
        // (MLP=CH, one L2 round-trip per tile), then all STS
        int T = cnt * CH;
        int sidx[CH];
        #pragma unroll
        for (int r = 0; r < CH; r++)
            sidx[r] = __shfl_sync(0xffffffffu, ent.x, e_[r]);
        float4 v[CH];
        #pragma unroll
        for (int r = 0; r < CH; r++)
            if (r * 32 + lane < T)
                v[r] = __ldg(g_xall + (size_t)sidx[r] * 8 + c_[r]);
        #pragma unroll
        for (int r = 0; r < CH; r++)
            if (r * 32 + lane < T)
                *(float4*)(ws + e_[r] * S + c_[r] * 4) = v[r];
        __syncwarp();

        if (lane < cnt) {
            float w = dn * __int_as_float(ent.y);
            const float* xe = ws + lane * S;
            float xl[L][8];
            #pragma unroll
            for (int l = 0; l < L; l++) {
                float4 a = *(const float4*)(xe + l * 8);
                float4 b = *(const float4*)(xe + l * 8 + 4);
                xl[l][0] = a.x; xl[l][1] = a.y; xl[l][2] = a.z; xl[l][3] = a.w;
                xl[l][4] = b.x; xl[l][5] = b.y; xl[l][6] = b.z; xl[l][7] = b.w;
            }
            float at[2][L];
            if (L == 1) {
                at[0][0] = 1.0f; at[1][0] = 1.0f;   // softmax over 1 elem
            } else {
                #pragma unroll
                for (int h = 0; h < 2; h++) {
                    float sc[L];
                    #pragma unroll
                    for (int l = 0; l < L; l++) {
                        float s_ = (h == 0) ? qb0 : qb1;
                        #pragma unroll
                        for (int d = 0; d < 4; d++)
                            s_ = fmaf(qk[h * 4 + d], xl[l][h * 4 + d], s_);
                        sc[l] = s_;
                    }
                    float m = sc[0];
                    #pragma unroll
                    for (int l = 1; l < L; l++) m = fmaxf(m, sc[l]);
                    float sm = 0.0f;
                    #pragma unroll
                    for (int l = 0; l < L; l++) { at[h][l] = __expf(sc[l] - m); sm += at[h][l]; }
                    float inv = 1.0f / sm;
                    #pragma unroll
                    for (int l = 0; l < L; l++) at[h][l] *= inv;
                }
            }
            // sum attn = 1  =>  msg_c = bv_c + wv_c * sum_l attn_l * x_l,c
            #pragma unroll
            for (int c = 0; c < 8; c++) {
                int h = c >> 2;
                float tmp = 0.0f;
                #pragma unroll
                for (int l = 0; l < L; l++) tmp = fmaf(at[h][l], xl[l][c], tmp);
                acc[c] = fmaf(w, fmaf(wv[c], tmp, bv[c]), acc[c]);
            }
        }
        __syncwarp();
    }

    #pragma unroll
    for (int o = 16; o; o >>= 1) {
        #pragma unroll
        for (int c = 0; c < 8; c++) acc[c] += __shfl_xor_sync(0xffffffffu, acc[c], o);
    }
    if (lane == 0) {
        float4* outp = g_xall + (size_t)n * 8 + L * 2;
        outp[0] = make_float4(fmaxf(acc[0], 0.f), fmaxf(acc[1], 0.f),
                              fmaxf(acc[2], 0.f), fmaxf(acc[3], 0.f));
        outp[1] = make_float4(fmaxf(acc[4], 0.f), fmaxf(acc[5], 0.f),
                              fmaxf(acc[6], 0.f), fmaxf(acc[7], 0.f));
    }
}

// ---------------- output head: logits + log_softmax ----------------

__global__ void out_kernel(const float* __restrict__ W2,
                           const float* __restrict__ b2,
                           float* __restrict__ out) {
    int n = blockIdx.x * blockDim.x + threadIdx.x;
    if (n >= N_NODES) return;
    float4 a = __ldg(g_xall + (size_t)n * 8 + 6);
    float4 b = __ldg(g_xall + (size_t)n * 8 + 7);
    float xl[8] = {a.x, a.y, a.z, a.w, b.x, b.y, b.z, b.w};
    float z0 = __ldg(b2 + 0), z1 = __ldg(b2 + 1);
    #pragma unroll
    for (int c = 0; c < 8; c++) {
        z0 = fmaf(xl[c], __ldg(W2 + c * 2 + 0), z0);
        z1 = fmaf(xl[c], __ldg(W2 + c * 2 + 1), z1);
    }
    float m = fmaxf(z0, z1);
    float lse = m + __logf(__expf(z0 - m) + __expf(z1 - m));
    out[(size_t)n * 2 + 0] = z0 - lse;
    out[(size_t)n * 2 + 1] = z1 - lse;
}

// ---------------- launch ----------------

extern "C" void kernel_launch(void* const* d_in, const int* in_sizes, int n_in,
                              void* d_out, int out_size) {
    const float* x    = (const float*)d_in[0];
    const int*   nidx = (const int*)  d_in[1];
    const int*   eidx = (const int*)  d_in[3];   // [2, E]
    const float* emb  = (const float*)d_in[5];
    const float* W1   = (const float*)d_in[6];
    const float* b1   = (const float*)d_in[7];
    const float* Wq   = (const float*)d_in[8];
    const float* bq   = (const float*)d_in[9];
    const float* Wk   = (const float*)d_in[10];
    const float* bk   = (const float*)d_in[11];
    const float* Wv   = (const float*)d_in[12];
    const float* bv   = (const float*)d_in[13];
    const float* W2   = (const float*)d_in[14];
    const float* b2   = (const float*)d_in[15];
    float* out = (float*)d_out;

    const int* src = eidx;
    const int* dst = eidx + N_EDGES;

    int nb_n = (N_NODES + 255) / 256;
    int nb_e = (N_EDGES + 255) / 256;

    count_kernel<<<nb_e, 256>>>(dst);
    scan1_kernel<<<SCAN_NBLK, SCAN_BLOCK>>>();
    scan2_kernel<<<1, 128>>>();
    scan3_fill_mlp_kernel<<<SCAN_NBLK, SCAN_BLOCK>>>(x, nidx, emb, W1, b1);
    fill_edges_kernel<<<nb_e, 256>>>(src, dst);

    int nb_c = (N_NODES + 7) / 8;   // warp per node, 8 warps/block
    conv_kernel<1><<<nb_c, 256>>>(Wq + 0,  bq + 0,  Wk + 0,  bk + 0,  Wv + 0,  bv + 0);
    conv_kernel<2><<<nb_c, 256>>>(Wq + 8,  bq + 8,  Wk + 8,  bk + 8,  Wv + 8,  bv + 8);
    conv_kernel<3><<<nb_c, 256>>>(Wq + 16, bq + 16, Wk + 16, bk + 16, Wv + 16, bv + 16);

    out_kernel<<<nb_n, 256>>>(W2, b2, out);
}

// round 4
// speedup vs baseline: 1.5874x; 1.5874x over previous
#include <cuda_runtime.h>
#include <math.h>

#define N_NODES 100000
#define N_EDGES 3200000
#define TOT_SLOTS (N_EDGES + N_NODES)
#define SCAN_BLOCK 1024
#define SCAN_NBLK ((N_NODES + SCAN_BLOCK - 1) / SCAN_BLOCK)   // 98

// Device-global scratch (zero-initialized at load; every kernel_launch leaves
// g_deg and g_acc zeroed again -> deterministic across graph replays).
// g_xall: 128B record per node, [level 0..3][c 0..7] -> one L1 line per node.
__device__ float4 g_xall[(size_t)N_NODES * 8];
__device__ float4 g_acc[(size_t)N_NODES * 2];     // per-layer accumulator
__device__ float  g_dinv[N_NODES];
__device__ int    g_deg[N_NODES];
__device__ int    g_off[N_NODES + 1];
__device__ int    g_cursor[N_NODES];
__device__ int4   g_csr[TOT_SLOTS];   // {src, f2i(dinv[src]), dst, 0}
__device__ int    g_bsum[SCAN_NBLK];

// ---------------- CSR build ----------------

__global__ void count_kernel(const int* __restrict__ dst) {
    int e = blockIdx.x * blockDim.x + threadIdx.x;
    if (e < N_EDGES) atomicAdd(&g_deg[dst[e]], 1);
}

// deg(+self) -> dinv, re-zero deg, block-exclusive scan
__global__ void scan1_kernel() {
    __shared__ int sh[SCAN_BLOCK];
    int i = blockIdx.x * SCAN_BLOCK + threadIdx.x;
    int v = 0;
    if (i < N_NODES) {
        v = g_deg[i] + 1;                 // +1 self loop
        g_dinv[i] = rsqrtf((float)v);
        g_deg[i] = 0;                     // restore entry invariant
    }
    sh[threadIdx.x] = v;
    __syncthreads();
    #pragma unroll
    for (int o = 1; o < SCAN_BLOCK; o <<= 1) {
        int t = 0;
        if ((int)threadIdx.x >= o) t = sh[threadIdx.x - o];
        __syncthreads();
        sh[threadIdx.x] += t;
        __syncthreads();
    }
    if (i < N_NODES) g_off[i] = sh[threadIdx.x] - v;
    if (threadIdx.x == SCAN_BLOCK - 1) g_bsum[blockIdx.x] = sh[SCAN_BLOCK - 1];
}

__global__ void scan2_kernel() {
    __shared__ int sh[128];
    int t = threadIdx.x;
    int v = (t < SCAN_NBLK) ? g_bsum[t] : 0;
    sh[t] = v;
    __syncthreads();
    #pragma unroll
    for (int o = 1; o < 128; o <<= 1) {
        int x = 0;
        if (t >= o) x = sh[t - o];
        __syncthreads();
        sh[t] += x;
        __syncthreads();
    }
    if (t < SCAN_NBLK) g_bsum[t] = sh[t] - v;
}

// scan fixup + self-loop CSR entry + cursor init + input MLP
__global__ void scan3_fill_mlp_kernel(const float* __restrict__ x,
                                      const int* __restrict__ node_index,
                                      const float* __restrict__ emb,
                                      const float* __restrict__ W1,
                                      const float* __restrict__ b1) {
    __shared__ float sW[24 * 8 + 8];
    int t = threadIdx.x;
    if (t < 192) sW[t] = W1[t];
    else if (t < 200) sW[t] = b1[t - 192];
    __syncthreads();

    int i = blockIdx.x * SCAN_BLOCK + t;
    if (i == 0) g_off[N_NODES] = TOT_SLOTS;
    if (i >= N_NODES) return;

    int off = g_off[i] + g_bsum[blockIdx.x];
    g_off[i] = off;
    int dv = __float_as_int(g_dinv[i]);
    g_csr[off] = make_int4(i, dv, i, 0);
    g_cursor[i] = off + 1;

    float in[24];
    int idx = node_index[i];
    #pragma unroll
    for (int j = 0; j < 8; j++) in[j] = emb[(size_t)idx * 8 + j];
    #pragma unroll
    for (int j = 0; j < 16; j++) in[8 + j] = x[(size_t)i * 16 + j];
    float o[8];
    #pragma unroll
    for (int c = 0; c < 8; c++) {
        float s = sW[192 + c];
        #pragma unroll
        for (int j = 0; j < 24; j++) s = fmaf(in[j], sW[j * 8 + c], s);
        o[c] = fmaxf(s, 0.0f);
    }
    float4* outp = g_xall + (size_t)i * 8;
    outp[0] = make_float4(o[0], o[1], o[2], o[3]);
    outp[1] = make_float4(o[4], o[5], o[6], o[7]);
}

__global__ void fill_edges_kernel(const int* __restrict__ src, const int* __restrict__ dst) {
    int e = blockIdx.x * blockDim.x + threadIdx.x;
    if (e < N_EDGES) {
        int s = src[e];
        int d = dst[e];
        int p = atomicAdd(&g_cursor[d], 1);
        g_csr[p] = make_int4(s, __float_as_int(g_dinv[s]), d, 0);
    }
}

// ---------------- DNA conv: edge-parallel + warp segmented reduction ------

template <int L>
__global__ void __launch_bounds__(256) econv_kernel(
    const float* __restrict__ Wq, const float* __restrict__ Bq,
    const float* __restrict__ Wk, const float* __restrict__ Bk,
    const float* __restrict__ Wv, const float* __restrict__ Bv)
{
    constexpr int CH = 2 * L;       // 16B chunks per edge
    constexpr int S  = 8 * L + 4;   // smem floats per edge (pad)
    __shared__ float sx[8 * 32 * S];

    int warp = threadIdx.x >> 5, lane = threadIdx.x & 31;
    int base = (blockIdx.x * 8 + warp) * 32;
    if (base >= TOT_SLOTS) return;            // warp-uniform
    float* ws = sx + warp * (32 * S);

    int cnt = min(32, TOT_SLOTS - base);
    bool valid = lane < cnt;
    int4 ent = make_int4(0, 0, -1, 0);
    if (valid) ent = __ldg(&g_csr[base + lane]);
    int dst = ent.z;

    // cooperative gather of src records into smem (~1 L1 line per edge)
    int T = cnt * CH;
    #pragma unroll
    for (int r = 0; r < CH; r++) {
        int idx = r * 32 + lane;
        int ci = min(idx, T - 1);
        int e = ci / CH, c = ci - e * CH;
        int s = __shfl_sync(0xffffffffu, ent.x, e);
        if (idx < T)
            *(float4*)(ws + e * S + c * 4) = __ldg(g_xall + (size_t)s * 8 + c);
    }
    __syncwarp();

    float m[8] = {0.f, 0.f, 0.f, 0.f, 0.f, 0.f, 0.f, 0.f};
    if (valid) {
        float wv[8], bvv[8];
        #pragma unroll
        for (int c = 0; c < 8; c++) { wv[c] = __ldg(Wv + c); bvv[c] = __ldg(Bv + c); }

        float w = __int_as_float(ent.y) * __ldg(&g_dinv[dst]);

        const float* xe = ws + lane * S;
        float xl[L][8];
        #pragma unroll
        for (int l = 0; l < L; l++) {
            float4 a = *(const float4*)(xe + l * 8);
            float4 b = *(const float4*)(xe + l * 8 + 4);
            xl[l][0] = a.x; xl[l][1] = a.y; xl[l][2] = a.z; xl[l][3] = a.w;
            xl[l][4] = b.x; xl[l][5] = b.y; xl[l][6] = b.z; xl[l][7] = b.w;
        }

        float at[2][L];
        if (L == 1) {
            at[0][0] = 1.0f; at[1][0] = 1.0f;
        } else {
            // q from dst's latest level (dst ~uniform in warp -> ~2 lines)
            float4 qa = __ldg(g_xall + (size_t)dst * 8 + (L - 1) * 2);
            float4 qb = __ldg(g_xall + (size_t)dst * 8 + (L - 1) * 2 + 1);
            float xq[8] = {qa.x, qa.y, qa.z, qa.w, qb.x, qb.y, qb.z, qb.w};
            float qk[8], qb0 = 0.f, qb1 = 0.f;
            #pragma unroll
            for (int c = 0; c < 8; c++) {
                float q = fmaf(xq[c], __ldg(Wq + c), __ldg(Bq + c));
                qk[c] = 0.5f * q * __ldg(Wk + c);             // fold 1/sqrt(d)
                float t = 0.5f * q * __ldg(Bk + c);
                if (c < 4) qb0 += t; else qb1 += t;
            }
            #pragma unroll
            for (int h = 0; h < 2; h++) {
                float sc[L];
                #pragma unroll
                for (int l = 0; l < L; l++) {
                    float s_ = (h == 0) ? qb0 : qb1;
                    #pragma unroll
                    for (int d = 0; d < 4; d++)
                        s_ = fmaf(qk[h * 4 + d], xl[l][h * 4 + d], s_);
                    sc[l] = s_;
                }
                float mx = sc[0];
                #pragma unroll
                for (int l = 1; l < L; l++) mx = fmaxf(mx, sc[l]);
                float sm = 0.0f;
                #pragma unroll
                for (int l = 0; l < L; l++) { at[h][l] = __expf(sc[l] - mx); sm += at[h][l]; }
                float inv = 1.0f / sm;
                #pragma unroll
                for (int l = 0; l < L; l++) at[h][l] *= inv;
            }
        }
        // sum attn = 1 => msg_c = w * (bv_c + wv_c * sum_l attn*x)
        #pragma unroll
        for (int c = 0; c < 8; c++) {
            int h = c >> 2;
            float t = 0.0f;
            #pragma unroll
            for (int l = 0; l < L; l++) t = fmaf(at[h][l], xl[l][c], t);
            m[c] = w * fmaf(wv[c], t, bvv[c]);
        }
    }

    // warp segmented inclusive scan keyed by dst (hoist predicates)
    #pragma unroll
    for (int off = 1; off < 32; off <<= 1) {
        int d2 = __shfl_up_sync(0xffffffffu, dst, off);
        bool take = (lane >= off) && (d2 == dst);
        #pragma unroll
        for (int c = 0; c < 8; c++) {
            float t = __shfl_up_sync(0xffffffffu, m[c], off);
            if (take) m[c] += t;
        }
    }
    int dn_ = __shfl_down_sync(0xffffffffu, dst, 1);
    bool segend = (lane == 31) || (dn_ != dst);
    if (valid && segend) {
        float* accp = (float*)g_acc + (size_t)dst * 8;
        #pragma unroll
        for (int c = 0; c < 8; c++) atomicAdd(accp + c, m[c]);
    }
}

// layer epilogue: relu(acc) -> x_all level, re-zero acc; FINAL fuses out head
template <int L, bool FINAL>
__global__ void epi_kernel(const float* __restrict__ W2,
                           const float* __restrict__ b2,
                           float* __restrict__ out) {
    int n = blockIdx.x * blockDim.x + threadIdx.x;
    if (n >= N_NODES) return;
    float4 a = g_acc[(size_t)n * 2];
    float4 b = g_acc[(size_t)n * 2 + 1];
    a.x = fmaxf(a.x, 0.f); a.y = fmaxf(a.y, 0.f); a.z = fmaxf(a.z, 0.f); a.w = fmaxf(a.w, 0.f);
    b.x = fmaxf(b.x, 0.f); b.y = fmaxf(b.y, 0.f); b.z = fmaxf(b.z, 0.f); b.w = fmaxf(b.w, 0.f);
    float4 z4 = make_float4(0.f, 0.f, 0.f, 0.f);
    g_acc[(size_t)n * 2] = z4;
    g_acc[(size_t)n * 2 + 1] = z4;
    if (!FINAL) {
        g_xall[(size_t)n * 8 + L * 2]     = a;
        g_xall[(size_t)n * 8 + L * 2 + 1] = b;
    } else {
        float xl[8] = {a.x, a.y, a.z, a.w, b.x, b.y, b.z, b.w};
        float z0 = __ldg(b2 + 0), z1 = __ldg(b2 + 1);
        #pragma unroll
        for (int c = 0; c < 8; c++) {
            z0 = fmaf(xl[c], __ldg(W2 + c * 2 + 0), z0);
            z1 = fmaf(xl[c], __ldg(W2 + c * 2 + 1), z1);
        }
        float mx = fmaxf(z0, z1);
        float lse = mx + __logf(__expf(z0 - mx) + __expf(z1 - mx));
        out[(size_t)n * 2 + 0] = z0 - lse;
        out[(size_t)n * 2 + 1] = z1 - lse;
    }
}

// ---------------- launch ----------------

extern "C" void kernel_launch(void* const* d_in, const int* in_sizes, int n_in,
                              void* d_out, int out_size) {
    const float* x    = (const float*)d_in[0];
    const int*   nidx = (const int*)  d_in[1];
    const int*   eidx = (const int*)  d_in[3];   // [2, E]
    const float* emb  = (const float*)d_in[5];
    const float* W1   = (const float*)d_in[6];
    const float* b1   = (const float*)d_in[7];
    const float* Wq   = (const float*)d_in[8];
    const float* bq   = (const float*)d_in[9];
    const float* Wk   = (const float*)d_in[10];
    const float* bk   = (const float*)d_in[11];
    const float* Wv   = (const float*)d_in[12];
    const float* bv   = (const float*)d_in[13];
    const float* W2   = (const float*)d_in[14];
    const float* b2   = (const float*)d_in[15];
    float* out = (float*)d_out;

    const int* src = eidx;
    const int* dst = eidx + N_EDGES;

    int nb_n = (N_NODES + 255) / 256;
    int nb_e = (N_EDGES + 255) / 256;
    int nb_c = (TOT_SLOTS + 255) / 256;   // edge-parallel: 8 warps x 32 slots

    count_kernel<<<nb_e, 256>>>(dst);
    scan1_kernel<<<SCAN_NBLK, SCAN_BLOCK>>>();
    scan2_kernel<<<1, 128>>>();
    scan3_fill_mlp_kernel<<<SCAN_NBLK, SCAN_BLOCK>>>(x, nidx, emb, W1, b1);
    fill_edges_kernel<<<nb_e, 256>>>(src, dst);

    econv_kernel<1><<<nb_c, 256>>>(Wq + 0,  bq + 0,  Wk + 0,  bk + 0,  Wv + 0,  bv + 0);
    epi_kernel<1, false><<<nb_n, 256>>>(W2, b2, out);
    econv_kernel<2><<<nb_c, 256>>>(Wq + 8,  bq + 8,  Wk + 8,  bk + 8,  Wv + 8,  bv + 8);
    epi_kernel<2, false><<<nb_n, 256>>>(W2, b2, out);
    econv_kernel<3><<<nb_c, 256>>>(Wq + 16, bq + 16, Wk + 16, bk + 16, Wv + 16, bv + 16);
    epi_kernel<3, true><<<nb_n, 256>>>(W2, b2, out);
}

// round 6
// speedup vs baseline: 1.6969x; 1.0690x over previous
#include <cuda_runtime.h>
#include <math.h>

#define N_NODES 100000
#define N_EDGES 3200000
#define TOT_SLOTS (N_EDGES + N_NODES)
#define SCAN_BLOCK 1024
#define SCAN_NBLK ((N_NODES + SCAN_BLOCK - 1) / SCAN_BLOCK)   // 98

// Device-global scratch (zero-init at load; g_deg/g_acc re-zeroed each run).
// g_xall: 128B record per node, [level 0..3][c 0..7] -> one L1 line per node.
__device__ float4 g_xall[(size_t)N_NODES * 8];
__device__ float4 g_acc[(size_t)N_NODES * 2];     // per-layer accumulator
__device__ float4 g_q[(size_t)N_NODES * 3];       // per-node {qk0..3},{qk4..7},{qb0,qb1,-,-}
__device__ float  g_dinv[N_NODES];
__device__ int    g_deg[N_NODES];
__device__ int    g_off[N_NODES + 1];
__device__ int    g_cursor[N_NODES];
__device__ int4   g_csr[TOT_SLOTS];   // {src, f2i(dinv[src]*dinv[dst]), dst, 0}
__device__ int    g_bsum[SCAN_NBLK];

// ---------------- CSR build ----------------

__global__ void count_kernel(const int4* __restrict__ dst4) {
    int e = blockIdx.x * blockDim.x + threadIdx.x;
    if (e < N_EDGES / 4) {
        int4 d = __ldg(&dst4[e]);
        atomicAdd(&g_deg[d.x], 1);
        atomicAdd(&g_deg[d.y], 1);
        atomicAdd(&g_deg[d.z], 1);
        atomicAdd(&g_deg[d.w], 1);
    }
}

// deg(+self) -> dinv, re-zero deg, block-exclusive scan
__global__ void scan1_kernel() {
    __shared__ int sh[SCAN_BLOCK];
    int i = blockIdx.x * SCAN_BLOCK + threadIdx.x;
    int v = 0;
    if (i < N_NODES) {
        v = g_deg[i] + 1;                 // +1 self loop
        g_dinv[i] = rsqrtf((float)v);
        g_deg[i] = 0;                     // restore entry invariant
    }
    sh[threadIdx.x] = v;
    __syncthreads();
    #pragma unroll
    for (int o = 1; o < SCAN_BLOCK; o <<= 1) {
        int t = 0;
        if ((int)threadIdx.x >= o) t = sh[threadIdx.x - o];
        __syncthreads();
        sh[threadIdx.x] += t;
        __syncthreads();
    }
    if (i < N_NODES) g_off[i] = sh[threadIdx.x] - v;
    if (threadIdx.x == SCAN_BLOCK - 1) g_bsum[blockIdx.x] = sh[SCAN_BLOCK - 1];
}

__global__ void scan2_kernel() {
    __shared__ int sh[128];
    int t = threadIdx.x;
    int v = (t < SCAN_NBLK) ? g_bsum[t] : 0;
    sh[t] = v;
    __syncthreads();
    #pragma unroll
    for (int o = 1; o < 128; o <<= 1) {
        int x = 0;
        if (t >= o) x = sh[t - o];
        __syncthreads();
        sh[t] += x;
        __syncthreads();
    }
    if (t < SCAN_NBLK) g_bsum[t] = sh[t] - v;
}

// scan fixup + self-loop CSR entry + cursor init + input MLP
__global__ void scan3_fill_mlp_kernel(const float* __restrict__ x,
                                      const int* __restrict__ node_index,
                                      const float* __restrict__ emb,
                                      const float* __restrict__ W1,
                                      const float* __restrict__ b1) {
    __shared__ float sW[24 * 8 + 8];
    int t = threadIdx.x;
    if (t < 192) sW[t] = W1[t];
    else if (t < 200) sW[t] = b1[t - 192];
    __syncthreads();

    int i = blockIdx.x * SCAN_BLOCK + t;
    if (i == 0) g_off[N_NODES] = TOT_SLOTS;
    if (i >= N_NODES) return;

    int off = g_off[i] + g_bsum[blockIdx.x];
    g_off[i] = off;
    float di = g_dinv[i];
    g_csr[off] = make_int4(i, __float_as_int(di * di), i, 0);
    g_cursor[i] = off + 1;

    float in[24];
    int idx = node_index[i];
    #pragma unroll
    for (int j = 0; j < 8; j++) in[j] = emb[(size_t)idx * 8 + j];
    #pragma unroll
    for (int j = 0; j < 16; j++) in[8 + j] = x[(size_t)i * 16 + j];
    float o[8];
    #pragma unroll
    for (int c = 0; c < 8; c++) {
        float s = sW[192 + c];
        #pragma unroll
        for (int j = 0; j < 24; j++) s = fmaf(in[j], sW[j * 8 + c], s);
        o[c] = fmaxf(s, 0.0f);
    }
    float4* outp = g_xall + (size_t)i * 8;
    outp[0] = make_float4(o[0], o[1], o[2], o[3]);
    outp[1] = make_float4(o[4], o[5], o[6], o[7]);
}

__global__ void fill_edges_kernel(const int* __restrict__ src, const int* __restrict__ dst) {
    int e = blockIdx.x * blockDim.x + threadIdx.x;
    if (e < N_EDGES) {
        int s = src[e];
        int d = dst[e];
        float w = g_dinv[s] * g_dinv[d];
        int p = atomicAdd(&g_cursor[d], 1);
        g_csr[p] = make_int4(s, __float_as_int(w), d, 0);
    }
}

// ---------------- DNA conv: edge-parallel + shfl segmented reduction ------

template <int L>
__global__ void __launch_bounds__(256) econv_kernel(
    const float* __restrict__ Wv, const float* __restrict__ Bv)
{
    constexpr int CH = 2 * L;       // 16B chunks per edge
    constexpr int S  = 8 * L + 4;   // smem floats per edge (pad)
    __shared__ float sx[8 * 32 * S];

    int warp = threadIdx.x >> 5, lane = threadIdx.x & 31;
    int base = (blockIdx.x * 8 + warp) * 32;
    if (base >= TOT_SLOTS) return;            // warp-uniform
    float* ws = sx + warp * (32 * S);

    int cnt = min(32, TOT_SLOTS - base);
    bool valid = lane < cnt;
    int4 ent = make_int4(0, 0, -1, 0);
    if (valid) ent = __ldg(&g_csr[base + lane]);
    int dst = ent.z;

    // cooperative gather of src records into smem (~1 L1 line per edge)
    int T = cnt * CH;
    #pragma unroll
    for (int r = 0; r < CH; r++) {
        int idx = r * 32 + lane;
        int ci = min(idx, T - 1);
        int e = ci / CH, c = ci - e * CH;
        int s = __shfl_sync(0xffffffffu, ent.x, e);
        if (idx < T)
            *(float4*)(ws + e * S + c * 4) = __ldg(g_xall + (size_t)s * 8 + c);
    }
    __syncwarp();

    float m[8] = {0.f, 0.f, 0.f, 0.f, 0.f, 0.f, 0.f, 0.f};
    if (valid) {
        float w = __int_as_float(ent.y);
        const float* xe = ws + lane * S;
        float xl[L][8];
        #pragma unroll
        for (int l = 0; l < L; l++) {
            float4 a = *(const float4*)(xe + l * 8);
            float4 b = *(const float4*)(xe + l * 8 + 4);
            xl[l][0] = a.x; xl[l][1] = a.y; xl[l][2] = a.z; xl[l][3] = a.w;
            xl[l][4] = b.x; xl[l][5] = b.y; xl[l][6] = b.z; xl[l][7] = b.w;
        }

        float at[2][L];
        if (L == 1) {
            at[0][0] = 1.0f; at[1][0] = 1.0f;
        } else {
            // precomputed q coefficients for dst (from previous epilogue)
            float4 q0 = __ldg(g_q + (size_t)dst * 3);
            float4 q1 = __ldg(g_q + (size_t)dst * 3 + 1);
            float4 q2 = __ldg(g_q + (size_t)dst * 3 + 2);
            float qk[8] = {q0.x, q0.y, q0.z, q0.w, q1.x, q1.y, q1.z, q1.w};
            #pragma unroll
            for (int h = 0; h < 2; h++) {
                float qb = (h == 0) ? q2.x : q2.y;
                float sc[L];
                #pragma unroll
                for (int l = 0; l < L; l++) {
                    float s_ = qb;
                    #pragma unroll
                    for (int d = 0; d < 4; d++)
                        s_ = fmaf(qk[h * 4 + d], xl[l][h * 4 + d], s_);
                    sc[l] = s_;
                }
                float mx = sc[0];
                #pragma unroll
                for (int l = 1; l < L; l++) mx = fmaxf(mx, sc[l]);
                float sm = 0.0f;
                #pragma unroll
                for (int l = 0; l < L; l++) { at[h][l] = __expf(sc[l] - mx); sm += at[h][l]; }
                float inv = 1.0f / sm;
                #pragma unroll
                for (int l = 0; l < L; l++) at[h][l] *= inv;
            }
        }
        // sum attn = 1 => msg_c = w * (bv_c + wv_c * sum_l attn*x)
        #pragma unroll
        for (int c = 0; c < 8; c++) {
            int h = c >> 2;
            float t = 0.0f;
            #pragma unroll
            for (int l = 0; l < L; l++) t = fmaf(at[h][l], xl[l][c], t);
            m[c] = w * fmaf(__ldg(Wv + c), t, __ldg(Bv + c));
        }
    }

    // warp segmented inclusive scan keyed by dst
    #pragma unroll
    for (int off = 1; off < 32; off <<= 1) {
        int d2 = __shfl_up_sync(0xffffffffu, dst, off);
        bool take = (lane >= off) && (d2 == dst);
        #pragma unroll
        for (int c = 0; c < 8; c++) {
            float t = __shfl_up_sync(0xffffffffu, m[c], off);
            if (take) m[c] += t;
        }
    }
    int dn_ = __shfl_down_sync(0xffffffffu, dst, 1);
    bool segend = (lane == 31) || (dn_ != dst);
    if (valid && segend) {
        float* accp = (float*)g_acc + (size_t)dst * 8;
        #pragma unroll
        for (int c = 0; c < 8; c++) atomicAdd(accp + c, m[c]);
    }
}

// layer epilogue: relu(acc) -> x_all level, re-zero acc, precompute next-layer
// q coefficients; FINAL fuses the output head instead.
template <int L, bool FINAL>
__global__ void epi_kernel(const float* __restrict__ WqN, const float* __restrict__ BqN,
                           const float* __restrict__ WkN, const float* __restrict__ BkN,
                           const float* __restrict__ W2,  const float* __restrict__ b2,
                           float* __restrict__ out) {
    int n = blockIdx.x * blockDim.x + threadIdx.x;
    if (n >= N_NODES) return;
    float4 a = g_acc[(size_t)n * 2];
    float4 b = g_acc[(size_t)n * 2 + 1];
    a.x = fmaxf(a.x, 0.f); a.y = fmaxf(a.y, 0.f); a.z = fmaxf(a.z, 0.f); a.w = fmaxf(a.w, 0.f);
    b.x = fmaxf(b.x, 0.f); b.y = fmaxf(b.y, 0.f); b.z = fmaxf(b.z, 0.f); b.w = fmaxf(b.w, 0.f);
    float4 z4 = make_float4(0.f, 0.f, 0.f, 0.f);
    g_acc[(size_t)n * 2] = z4;
    g_acc[(size_t)n * 2 + 1] = z4;
    float xl[8] = {a.x, a.y, a.z, a.w, b.x, b.y, b.z, b.w};
    if (!FINAL) {
        g_xall[(size_t)n * 8 + L * 2]     = a;
        g_xall[(size_t)n * 8 + L * 2 + 1] = b;
        // next-layer attention coeffs: qk[c] = 0.5*q[c]*Wk[c], qb_h = sum 0.5*q*Bk
        float qk[8], qb0 = 0.f, qb1 = 0.f;
        #pragma unroll
        for (int c = 0; c < 8; c++) {
            float q = fmaf(xl[c], __ldg(WqN + c), __ldg(BqN + c));
            qk[c] = 0.5f * q * __ldg(WkN + c);              // fold 1/sqrt(d)
            float t = 0.5f * q * __ldg(BkN + c);
            if (c < 4) qb0 += t; else qb1 += t;
        }
        g_q[(size_t)n * 3]     = make_float4(qk[0], qk[1], qk[2], qk[3]);
        g_q[(size_t)n * 3 + 1] = make_float4(qk[4], qk[5], qk[6], qk[7]);
        g_q[(size_t)n * 3 + 2] = make_float4(qb0, qb1, 0.f, 0.f);
    } else {
        float z0 = __ldg(b2 + 0), z1 = __ldg(b2 + 1);
        #pragma unroll
        for (int c = 0; c < 8; c++) {
            z0 = fmaf(xl[c], __ldg(W2 + c * 2 + 0), z0);
            z1 = fmaf(xl[c], __ldg(W2 + c * 2 + 1), z1);
        }
        float mx = fmaxf(z0, z1);
        float lse = mx + __logf(__expf(z0 - mx) + __expf(z1 - mx));
        out[(size_t)n * 2 + 0] = z0 - lse;
        out[(size_t)n * 2 + 1] = z1 - lse;
    }
}

// ---------------- launch ----------------

extern "C" void kernel_launch(void* const* d_in, const int* in_sizes, int n_in,
                              void* d_out, int out_size) {
    const float* x    = (const float*)d_in[0];
    const int*   nidx = (const int*)  d_in[1];
    const int*   eidx = (const int*)  d_in[3];   // [2, E]
    const float* emb  = (const float*)d_in[5];
    const float* W1   = (const float*)d_in[6];
    const float* b1   = (const float*)d_in[7];
    const float* Wq   = (const float*)d_in[8];
    const float* bq   = (const float*)d_in[9];
    const float* Wk   = (const float*)d_in[10];
    const float* bk   = (const float*)d_in[11];
    const float* Wv   = (const float*)d_in[12];
    const float* bv   = (const float*)d_in[13];
    const float* W2   = (const float*)d_in[14];
    const float* b2   = (const float*)d_in[15];
    float* out = (float*)d_out;

    const int* src = eidx;
    const int* dst = eidx + N_EDGES;

    int nb_n  = (N_NODES + 255) / 256;
    int nb_e  = (N_EDGES + 255) / 256;
    int nb_e4 = (N_EDGES / 4 + 255) / 256;
    int nb_c  = (TOT_SLOTS + 255) / 256;   // edge-parallel: 8 warps x 32 slots

    count_kernel<<<nb_e4, 256>>>((const int4*)dst);
    scan1_kernel<<<SCAN_NBLK, SCAN_BLOCK>>>();
    scan2_kernel<<<1, 128>>>();
    scan3_fill_mlp_kernel<<<SCAN_NBLK, SCAN_BLOCK>>>(x, nidx, emb, W1, b1);
    fill_edges_kernel<<<nb_e, 256>>>(src, dst);

    econv_kernel<1><<<nb_c, 256>>>(Wv + 0, bv + 0);
    epi_kernel<1, false><<<nb_n, 256>>>(Wq + 8,  bq + 8,  Wk + 8,  bk + 8,  W2, b2, out);
    econv_kernel<2><<<nb_c, 256>>>(Wv + 8, bv + 8);
    epi_kernel<2, false><<<nb_n, 256>>>(Wq + 16, bq + 16, Wk + 16, bk + 16, W2, b2, out);
    econv_kernel<3><<<nb_c, 256>>>(Wv + 16, bv + 16);
    epi_kernel<3, true><<<nb_n, 256>>>(Wq, bq, Wk, bk, W2, b2, out);
}

// round 7
// speedup vs baseline: 1.7342x; 1.0220x over previous
#include <cuda_runtime.h>
#include <math.h>

#define N_NODES 100000
#define N_EDGES 3200000
#define TOT_SLOTS (N_EDGES + N_NODES)
#define SCAN_BLOCK 1024
#define SCAN_NBLK ((N_NODES + SCAN_BLOCK - 1) / SCAN_BLOCK)   // 98

// Device-global scratch (zero-init at load; g_deg/g_acc re-zeroed each run).
__device__ float4 g_x0[(size_t)N_NODES * 2];   // level-0 features (32B/node)
__device__ float4 g_y [(size_t)N_NODES * 2];   // conv1 operand: dinv*(bv1+wv1*x0)
__device__ float4 g_r2[(size_t)N_NODES * 4];   // conv2 operand: {x1, x0-x1} 64B
__device__ float4 g_r3[(size_t)N_NODES * 8];   // conv3 operand: {x2, x0-x2, x1-x2, pad} 128B
__device__ float4 g_acc[(size_t)N_NODES * 2];  // per-layer accumulator
__device__ float4 g_q[(size_t)N_NODES * 2];    // per-node qk[8] (0.5*q*wk)
__device__ float  g_dinv[N_NODES];
__device__ int    g_deg[N_NODES];
__device__ int    g_off[N_NODES + 1];
__device__ int    g_cursor[N_NODES];
__device__ int4   g_csr[TOT_SLOTS];   // {src, f2i(dinv[src]*dinv[dst]), dst, 0}
__device__ int    g_bsum[SCAN_NBLK];

// ---- packed f32x2 helpers (sm_103a) ----
__device__ __forceinline__ unsigned long long ADDX2(unsigned long long a, unsigned long long b) {
    unsigned long long r;
    asm("add.rn.f32x2 %0, %1, %2;" : "=l"(r) : "l"(a), "l"(b));
    return r;
}
__device__ __forceinline__ unsigned long long PACK2(float lo, float hi) {
    unsigned long long r;
    asm("mov.b64 %0, {%1, %2};" : "=l"(r) : "f"(lo), "f"(hi));
    return r;
}
__device__ __forceinline__ void UNPACK2(unsigned long long v, float& lo, float& hi) {
    asm("mov.b64 {%0, %1}, %2;" : "=f"(lo), "=f"(hi) : "l"(v));
}

// segmented warp reduction keyed by dst + vectorized atomic flush
__device__ __forceinline__ void segreduce_flush(float m[8], int dst, int lane, bool valid) {
    unsigned long long p[4];
    #pragma unroll
    for (int i = 0; i < 4; i++) p[i] = PACK2(m[2 * i], m[2 * i + 1]);
    #pragma unroll
    for (int off = 1; off < 32; off <<= 1) {
        int d2 = __shfl_up_sync(0xffffffffu, dst, off);
        bool take = (lane >= off) && (d2 == dst);
        #pragma unroll
        for (int i = 0; i < 4; i++) {
            unsigned long long t = __shfl_up_sync(0xffffffffu, p[i], off);
            if (take) p[i] = ADDX2(p[i], t);
        }
    }
    int dn = __shfl_down_sync(0xffffffffu, dst, 1);
    if (valid && (lane == 31 || dn != dst)) {
        float r[8];
        UNPACK2(p[0], r[0], r[1]); UNPACK2(p[1], r[2], r[3]);
        UNPACK2(p[2], r[4], r[5]); UNPACK2(p[3], r[6], r[7]);
        float* a = (float*)g_acc + (size_t)dst * 8;
        asm volatile("red.global.add.v4.f32 [%0], {%1,%2,%3,%4};"
                     :: "l"(a), "f"(r[0]), "f"(r[1]), "f"(r[2]), "f"(r[3]) : "memory");
        asm volatile("red.global.add.v4.f32 [%0], {%1,%2,%3,%4};"
                     :: "l"(a + 4), "f"(r[4]), "f"(r[5]), "f"(r[6]), "f"(r[7]) : "memory");
    }
}

// ---------------- CSR build ----------------

__global__ void count_kernel(const int4* __restrict__ dst4) {
    int e = blockIdx.x * blockDim.x + threadIdx.x;
    if (e < N_EDGES / 4) {
        int4 d = __ldg(&dst4[e]);
        atomicAdd(&g_deg[d.x], 1);
        atomicAdd(&g_deg[d.y], 1);
        atomicAdd(&g_deg[d.z], 1);
        atomicAdd(&g_deg[d.w], 1);
    }
}

__global__ void scan1_kernel() {
    __shared__ int sh[SCAN_BLOCK];
    int i = blockIdx.x * SCAN_BLOCK + threadIdx.x;
    int v = 0;
    if (i < N_NODES) {
        v = g_deg[i] + 1;                 // +1 self loop
        g_dinv[i] = rsqrtf((float)v);
        g_deg[i] = 0;                     // restore entry invariant
    }
    sh[threadIdx.x] = v;
    __syncthreads();
    #pragma unroll
    for (int o = 1; o < SCAN_BLOCK; o <<= 1) {
        int t = 0;
        if ((int)threadIdx.x >= o) t = sh[threadIdx.x - o];
        __syncthreads();
        sh[threadIdx.x] += t;
        __syncthreads();
    }
    if (i < N_NODES) g_off[i] = sh[threadIdx.x] - v;
    if (threadIdx.x == SCAN_BLOCK - 1) g_bsum[blockIdx.x] = sh[SCAN_BLOCK - 1];
}

__global__ void scan2_kernel() {
    __shared__ int sh[128];
    int t = threadIdx.x;
    int v = (t < SCAN_NBLK) ? g_bsum[t] : 0;
    sh[t] = v;
    __syncthreads();
    #pragma unroll
    for (int o = 1; o < 128; o <<= 1) {
        int x = 0;
        if (t >= o) x = sh[t - o];
        __syncthreads();
        sh[t] += x;
        __syncthreads();
    }
    if (t < SCAN_NBLK) g_bsum[t] = sh[t] - v;
}

// scan fixup + self-loop CSR + cursor + input MLP + conv1 operand y
__global__ void scan3_fill_mlp_kernel(const float* __restrict__ x,
                                      const int* __restrict__ node_index,
                                      const float* __restrict__ emb,
                                      const float* __restrict__ W1,
                                      const float* __restrict__ b1,
                                      const float* __restrict__ Wv1,
                                      const float* __restrict__ Bv1) {
    __shared__ float sW[24 * 8 + 8];
    int t = threadIdx.x;
    if (t < 192) sW[t] = W1[t];
    else if (t < 200) sW[t] = b1[t - 192];
    __syncthreads();

    int i = blockIdx.x * SCAN_BLOCK + t;
    if (i == 0) g_off[N_NODES] = TOT_SLOTS;
    if (i >= N_NODES) return;

    int off = g_off[i] + g_bsum[blockIdx.x];
    g_off[i] = off;
    float di = g_dinv[i];
    g_csr[off] = make_int4(i, __float_as_int(di * di), i, 0);
    g_cursor[i] = off + 1;

    float in[24];
    int idx = node_index[i];
    #pragma unroll
    for (int j = 0; j < 8; j++) in[j] = emb[(size_t)idx * 8 + j];
    #pragma unroll
    for (int j = 0; j < 16; j++) in[8 + j] = x[(size_t)i * 16 + j];
    float o[8], y[8];
    #pragma unroll
    for (int c = 0; c < 8; c++) {
        float s = sW[192 + c];
        #pragma unroll
        for (int j = 0; j < 24; j++) s = fmaf(in[j], sW[j * 8 + c], s);
        o[c] = fmaxf(s, 0.0f);
        y[c] = di * fmaf(__ldg(Wv1 + c), o[c], __ldg(Bv1 + c));
    }
    g_x0[(size_t)i * 2]     = make_float4(o[0], o[1], o[2], o[3]);
    g_x0[(size_t)i * 2 + 1] = make_float4(o[4], o[5], o[6], o[7]);
    g_y[(size_t)i * 2]      = make_float4(y[0], y[1], y[2], y[3]);
    g_y[(size_t)i * 2 + 1]  = make_float4(y[4], y[5], y[6], y[7]);
}

__global__ void fill_edges_kernel(const int* __restrict__ src, const int* __restrict__ dst) {
    int e = blockIdx.x * blockDim.x + threadIdx.x;
    if (e < N_EDGES) {
        int s = src[e];
        int d = dst[e];
        float w = g_dinv[s] * g_dinv[d];
        int p = atomicAdd(&g_cursor[d], 1);
        g_csr[p] = make_int4(s, __float_as_int(w), d, 0);
    }
}

// ---------------- conv1: pure SpMV of y (dinv[dst] applied in epi1) -------

__global__ void __launch_bounds__(256) econv1_kernel() {
    constexpr int S = 12;
    __shared__ float sx[8 * 32 * S];
    int warp = threadIdx.x >> 5, lane = threadIdx.x & 31;
    int base = (blockIdx.x * 8 + warp) * 32;
    if (base >= TOT_SLOTS) return;
    float* ws = sx + warp * (32 * S);

    int cnt = min(32, TOT_SLOTS - base);
    bool valid = lane < cnt;
    int4 ent = make_int4(0, 0, -1, 0);
    if (valid) ent = __ldg(&g_csr[base + lane]);
    int dst = ent.z;

    int T = cnt * 2;
    #pragma unroll
    for (int r = 0; r < 2; r++) {
        int idx = r * 32 + lane;
        int ci = min(idx, T - 1);
        int e = ci >> 1, c = ci & 1;
        int s = __shfl_sync(0xffffffffu, ent.x, e);
        if (idx < T)
            *(float4*)(ws + e * S + c * 4) = __ldg(g_y + (size_t)s * 2 + c);
    }
    __syncwarp();

    float m[8] = {0.f, 0.f, 0.f, 0.f, 0.f, 0.f, 0.f, 0.f};
    if (valid) {
        const float* xe = ws + lane * S;
        #pragma unroll
        for (int c = 0; c < 8; c++) m[c] = xe[c];
    }
    segreduce_flush(m, dst, lane, valid);
}

// ---------------- conv2: 2-level attention via sigmoid --------------------

__global__ void __launch_bounds__(256) econv2_kernel(
    const float* __restrict__ Wv, const float* __restrict__ Bv)
{
    constexpr int S = 20;
    __shared__ float sx[8 * 32 * S];
    int warp = threadIdx.x >> 5, lane = threadIdx.x & 31;
    int base = (blockIdx.x * 8 + warp) * 32;
    if (base >= TOT_SLOTS) return;
    float* ws = sx + warp * (32 * S);

    int cnt = min(32, TOT_SLOTS - base);
    bool valid = lane < cnt;
    int4 ent = make_int4(0, 0, -1, 0);
    if (valid) ent = __ldg(&g_csr[base + lane]);
    int dst = ent.z;

    int T = cnt * 4;
    #pragma unroll
    for (int r = 0; r < 4; r++) {
        int idx = r * 32 + lane;
        int ci = min(idx, T - 1);
        int e = ci >> 2, c = ci & 3;
        int s = __shfl_sync(0xffffffffu, ent.x, e);
        if (idx < T)
            *(float4*)(ws + e * S + c * 4) = __ldg(g_r2 + (size_t)s * 4 + c);
    }
    __syncwarp();

    float m[8] = {0.f, 0.f, 0.f, 0.f, 0.f, 0.f, 0.f, 0.f};
    if (valid) {
        float w = __int_as_float(ent.y);
        const float* xe = ws + lane * S;
        float x1[8], d01[8];
        #pragma unroll
        for (int c = 0; c < 8; c++) { x1[c] = xe[c]; d01[c] = xe[8 + c]; }
        float4 q0 = __ldg(g_q + (size_t)dst * 2);
        float4 q1 = __ldg(g_q + (size_t)dst * 2 + 1);
        float qk[8] = {q0.x, q0.y, q0.z, q0.w, q1.x, q1.y, q1.z, q1.w};
        float a[2];
        #pragma unroll
        for (int h = 0; h < 2; h++) {
            float s_ = 0.0f;
            #pragma unroll
            for (int d = 0; d < 4; d++) s_ = fmaf(qk[h * 4 + d], d01[h * 4 + d], s_);
            a[h] = 1.0f / (1.0f + __expf(-s_));      // sigmoid(s0 - s1)
        }
        #pragma unroll
        for (int c = 0; c < 8; c++) {
            float t = fmaf(a[c >> 2], d01[c], x1[c]);
            m[c] = w * fmaf(__ldg(Wv + c), t, __ldg(Bv + c));
        }
    }
    segreduce_flush(m, dst, lane, valid);
}

// ---------------- conv3: 3-level attention, delta form --------------------

__global__ void __launch_bounds__(256) econv3_kernel(
    const float* __restrict__ Wv, const float* __restrict__ Bv)
{
    constexpr int S = 28;
    __shared__ float sx[8 * 32 * S];
    int warp = threadIdx.x >> 5, lane = threadIdx.x & 31;
    int base = (blockIdx.x * 8 + warp) * 32;
    if (base >= TOT_SLOTS) return;
    float* ws = sx + warp * (32 * S);

    int cnt = min(32, TOT_SLOTS - base);
    bool valid = lane < cnt;
    int4 ent = make_int4(0, 0, -1, 0);
    if (valid) ent = __ldg(&g_csr[base + lane]);
    int dst = ent.z;

    int T = cnt * 6;
    #pragma unroll
    for (int r = 0; r < 6; r++) {
        int idx = r * 32 + lane;
        int ci = min(idx, T - 1);
        int e = ci / 6, c = ci - e * 6;
        int s = __shfl_sync(0xffffffffu, ent.x, e);
        if (idx < T)
            *(float4*)(ws + e * S + c * 4) = __ldg(g_r3 + (size_t)s * 8 + c);
    }
    __syncwarp();

    float m[8] = {0.f, 0.f, 0.f, 0.f, 0.f, 0.f, 0.f, 0.f};
    if (valid) {
        float w = __int_as_float(ent.y);
        const float* xe = ws + lane * S;
        float x2[8], d02[8], d12[8];
        #pragma unroll
        for (int c = 0; c < 8; c++) {
            x2[c] = xe[c]; d02[c] = xe[8 + c]; d12[c] = xe[16 + c];
        }
        float4 q0 = __ldg(g_q + (size_t)dst * 2);
        float4 q1 = __ldg(g_q + (size_t)dst * 2 + 1);
        float qk[8] = {q0.x, q0.y, q0.z, q0.w, q1.x, q1.y, q1.z, q1.w};
        float a0[2], a1[2];
        #pragma unroll
        for (int h = 0; h < 2; h++) {
            float t0 = 0.0f, t1 = 0.0f;
            #pragma unroll
            for (int d = 0; d < 4; d++) {
                t0 = fmaf(qk[h * 4 + d], d02[h * 4 + d], t0);
                t1 = fmaf(qk[h * 4 + d], d12[h * 4 + d], t1);
            }
            float mx = fmaxf(fmaxf(t0, t1), 0.0f);
            float e0 = __expf(t0 - mx), e1 = __expf(t1 - mx), e2 = __expf(-mx);
            float inv = 1.0f / (e0 + e1 + e2);
            a0[h] = e0 * inv; a1[h] = e1 * inv;
        }
        #pragma unroll
        for (int c = 0; c < 8; c++) {
            int h = c >> 2;
            float t = fmaf(a0[h], d02[c], fmaf(a1[h], d12[c], x2[c]));
            m[c] = w * fmaf(__ldg(Wv + c), t, __ldg(Bv + c));
        }
    }
    segreduce_flush(m, dst, lane, valid);
}

// ---------------- epilogues ----------------

// epi1: x1 = relu(dinv*acc); write {x1, x0-x1} record + layer-2 qk
__global__ void epi1_kernel(const float* __restrict__ Wq2, const float* __restrict__ Bq2,
                            const float* __restrict__ Wk2) {
    int n = blockIdx.x * blockDim.x + threadIdx.x;
    if (n >= N_NODES) return;
    float4 a = g_acc[(size_t)n * 2];
    float4 b = g_acc[(size_t)n * 2 + 1];
    float4 z4 = make_float4(0.f, 0.f, 0.f, 0.f);
    g_acc[(size_t)n * 2] = z4;
    g_acc[(size_t)n * 2 + 1] = z4;
    float di = g_dinv[n];
    float x1[8] = {fmaxf(di * a.x, 0.f), fmaxf(di * a.y, 0.f), fmaxf(di * a.z, 0.f), fmaxf(di * a.w, 0.f),
                   fmaxf(di * b.x, 0.f), fmaxf(di * b.y, 0.f), fmaxf(di * b.z, 0.f), fmaxf(di * b.w, 0.f)};
    float4 xa = g_x0[(size_t)n * 2];
    float4 xb = g_x0[(size_t)n * 2 + 1];
    float x0[8] = {xa.x, xa.y, xa.z, xa.w, xb.x, xb.y, xb.z, xb.w};
    g_r2[(size_t)n * 4]     = make_float4(x1[0], x1[1], x1[2], x1[3]);
    g_r2[(size_t)n * 4 + 1] = make_float4(x1[4], x1[5], x1[6], x1[7]);
    g_r2[(size_t)n * 4 + 2] = make_float4(x0[0] - x1[0], x0[1] - x1[1], x0[2] - x1[2], x0[3] - x1[3]);
    g_r2[(size_t)n * 4 + 3] = make_float4(x0[4] - x1[4], x0[5] - x1[5], x0[6] - x1[6], x0[7] - x1[7]);
    float qk[8];
    #pragma unroll
    for (int c = 0; c < 8; c++) {
        float q = fmaf(x1[c], __ldg(Wq2 + c), __ldg(Bq2 + c));
        qk[c] = 0.5f * q * __ldg(Wk2 + c);               // fold 1/sqrt(d)
    }
    g_q[(size_t)n * 2]     = make_float4(qk[0], qk[1], qk[2], qk[3]);
    g_q[(size_t)n * 2 + 1] = make_float4(qk[4], qk[5], qk[6], qk[7]);
}

// epi2: x2 = relu(acc); write {x2, x0-x2, x1-x2} record + layer-3 qk
__global__ void epi2_kernel(const float* __restrict__ Wq3, const float* __restrict__ Bq3,
                            const float* __restrict__ Wk3) {
    int n = blockIdx.x * blockDim.x + threadIdx.x;
    if (n >= N_NODES) return;
    float4 a = g_acc[(size_t)n * 2];
    float4 b = g_acc[(size_t)n * 2 + 1];
    float4 z4 = make_float4(0.f, 0.f, 0.f, 0.f);
    g_acc[(size_t)n * 2] = z4;
    g_acc[(size_t)n * 2 + 1] = z4;
    float x2[8] = {fmaxf(a.x, 0.f), fmaxf(a.y, 0.f), fmaxf(a.z, 0.f), fmaxf(a.w, 0.f),
                   fmaxf(b.x, 0.f), fmaxf(b.y, 0.f), fmaxf(b.z, 0.f), fmaxf(b.w, 0.f)};
    // recover x1 and x0 from g_r2 = {x1, x0-x1}
    float4 r0 = g_r2[(size_t)n * 4];
    float4 r1 = g_r2[(size_t)n * 4 + 1];
    float4 r2 = g_r2[(size_t)n * 4 + 2];
    float4 r3 = g_r2[(size_t)n * 4 + 3];
    float x1[8] = {r0.x, r0.y, r0.z, r0.w, r1.x, r1.y, r1.z, r1.w};
    float x0[8] = {r0.x + r2.x, r0.y + r2.y, r0.z + r2.z, r0.w + r2.w,
                   r1.x + r3.x, r1.y + r3.y, r1.z + r3.z, r1.w + r3.w};
    g_r3[(size_t)n * 8]     = make_float4(x2[0], x2[1], x2[2], x2[3]);
    g_r3[(size_t)n * 8 + 1] = make_float4(x2[4], x2[5], x2[6], x2[7]);
    g_r3[(size_t)n * 8 + 2] = make_float4(x0[0] - x2[0], x0[1] - x2[1], x0[2] - x2[2], x0[3] - x2[3]);
    g_r3[(size_t)n * 8 + 3] = make_float4(x0[4] - x2[4], x0[5] - x2[5], x0[6] - x2[6], x0[7] - x2[7]);
    g_r3[(size_t)n * 8 + 4] = make_float4(x1[0] - x2[0], x1[1] - x2[1], x1[2] - x2[2], x1[3] - x2[3]);
    g_r3[(size_t)n * 8 + 5] = make_float4(x1[4] - x2[4], x1[5] - x2[5], x1[6] - x2[6], x1[7] - x2[7]);
    float qk[8];
    #pragma unroll
    for (int c = 0; c < 8; c++) {
        float q = fmaf(x2[c], __ldg(Wq3 + c), __ldg(Bq3 + c));
        qk[c] = 0.5f * q * __ldg(Wk3 + c);
    }
    g_q[(size_t)n * 2]     = make_float4(qk[0], qk[1], qk[2], qk[3]);
    g_q[(size_t)n * 2 + 1] = make_float4(qk[4], qk[5], qk[6], qk[7]);
}

// epi3: x3 = relu(acc) -> logits -> log_softmax
__global__ void epi3_kernel(const float* __restrict__ W2, const float* __restrict__ b2,
                            float* __restrict__ out) {
    int n = blockIdx.x * blockDim.x + threadIdx.x;
    if (n >= N_NODES) return;
    float4 a = g_acc[(size_t)n * 2];
    float4 b = g_acc[(size_t)n * 2 + 1];
    float4 z4 = make_float4(0.f, 0.f, 0.f, 0.f);
    g_acc[(size_t)n * 2] = z4;
    g_acc[(size_t)n * 2 + 1] = z4;
    float xl[8] = {fmaxf(a.x, 0.f), fmaxf(a.y, 0.f), fmaxf(a.z, 0.f), fmaxf(a.w, 0.f),
                   fmaxf(b.x, 0.f), fmaxf(b.y, 0.f), fmaxf(b.z, 0.f), fmaxf(b.w, 0.f)};
    float z0 = __ldg(b2 + 0), z1 = __ldg(b2 + 1);
    #pragma unroll
    for (int c = 0; c < 8; c++) {
        z0 = fmaf(xl[c], __ldg(W2 + c * 2 + 0), z0);
        z1 = fmaf(xl[c], __ldg(W2 + c * 2 + 1), z1);
    }
    float mx = fmaxf(z0, z1);
    float lse = mx + __logf(__expf(z0 - mx) + __expf(z1 - mx));
    out[(size_t)n * 2 + 0] = z0 - lse;
    out[(size_t)n * 2 + 1] = z1 - lse;
}

// ---------------- launch ----------------

extern "C" void kernel_launch(void* const* d_in, const int* in_sizes, int n_in,
                              void* d_out, int out_size) {
    const float* x    = (const float*)d_in[0];
    const int*   nidx = (const int*)  d_in[1];
    const int*   eidx = (const int*)  d_in[3];   // [2, E]
    const float* emb  = (const float*)d_in[5];
    const float* W1   = (const float*)d_in[6];
    const float* b1   = (const float*)d_in[7];
    const float* Wq   = (const float*)d_in[8];
    const float* bq   = (const float*)d_in[9];
    const float* Wk   = (const float*)d_in[10];
    const float* Wv   = (const float*)d_in[12];
    const float* bv   = (const float*)d_in[13];
    const float* W2   = (const float*)d_in[14];
    const float* b2   = (const float*)d_in[15];
    float* out = (float*)d_out;

    const int* src = eidx;
    const int* dst = eidx + N_EDGES;

    int nb_n  = (N_NODES + 255) / 256;
    int nb_e  = (N_EDGES + 255) / 256;
    int nb_e4 = (N_EDGES / 4 + 255) / 256;
    int nb_c  = (TOT_SLOTS + 255) / 256;

    count_kernel<<<nb_e4, 256>>>((const int4*)dst);
    scan1_kernel<<<SCAN_NBLK, SCAN_BLOCK>>>();
    scan2_kernel<<<1, 128>>>();
    scan3_fill_mlp_kernel<<<SCAN_NBLK, SCAN_BLOCK>>>(x, nidx, emb, W1, b1, Wv + 0, bv + 0);
    fill_edges_kernel<<<nb_e, 256>>>(src, dst);

    econv1_kernel<<<nb_c, 256>>>();
    epi1_kernel<<<nb_n, 256>>>(Wq + 8, bq + 8, Wk + 8);
    econv2_kernel<<<nb_c, 256>>>(Wv + 8, bv + 8);
    epi2_kernel<<<nb_n, 256>>>(Wq + 16, bq + 16, Wk + 16);
    econv3_kernel<<<nb_c, 256>>>(Wv + 16, bv + 16);
    epi3_kernel<<<nb_n, 256>>>(W2, b2, out);
}

// round 8
// speedup vs baseline: 1.7855x; 1.0296x over previous
#include <cuda_runtime.h>
#include <math.h>

#define N_NODES 100000
#define N_EDGES 3200000
#define TOT_SLOTS (N_EDGES + N_NODES)
#define SCAN_BLOCK 1024
#define SCAN_NBLK ((N_NODES + SCAN_BLOCK - 1) / SCAN_BLOCK)   // 98

// Device-global scratch (zero-init at load; g_deg/g_acc re-zeroed each run).
__device__ float4 g_x0[(size_t)N_NODES * 2];   // level-0 features (32B/node)
__device__ float4 g_y [(size_t)N_NODES * 2];   // conv1 operand: dinv*(bv1+wv1*x0)
__device__ float4 g_r2[(size_t)N_NODES * 4];   // conv2 operand: {x1, x0-x1} 64B
__device__ float4 g_r3[(size_t)N_NODES * 8];   // conv3 operand: {x2, x0-x2, x1-x2, pad} 128B
__device__ float4 g_acc[(size_t)N_NODES * 2];  // per-layer accumulator
__device__ float4 g_q[(size_t)N_NODES * 2];    // per-node qk[8] (0.5*q*wk)
__device__ float  g_dinv[N_NODES];
__device__ int    g_deg[N_NODES];
__device__ int    g_off[N_NODES + 1];
__device__ int    g_cursor[N_NODES];
__device__ int4   g_csr[TOT_SLOTS];   // {src, f2i(dinv[src]), dst, 0}
__device__ int    g_bsum[SCAN_NBLK];

// ---- packed f32x2 helpers ----
__device__ __forceinline__ unsigned long long ADDX2(unsigned long long a, unsigned long long b) {
    unsigned long long r;
    asm("add.rn.f32x2 %0, %1, %2;" : "=l"(r) : "l"(a), "l"(b));
    return r;
}
__device__ __forceinline__ unsigned long long PACK2(float lo, float hi) {
    unsigned long long r;
    asm("mov.b64 %0, {%1, %2};" : "=l"(r) : "f"(lo), "f"(hi));
    return r;
}
__device__ __forceinline__ void UNPACK2(unsigned long long v, float& lo, float& hi) {
    asm("mov.b64 {%0, %1}, %2;" : "=f"(lo), "=f"(hi) : "l"(v));
}
__device__ __forceinline__ void flush8(int dst, const float r[8]) {
    float* a = (float*)g_acc + (size_t)dst * 8;
    asm volatile("red.global.add.v4.f32 [%0], {%1,%2,%3,%4};"
                 :: "l"(a), "f"(r[0]), "f"(r[1]), "f"(r[2]), "f"(r[3]) : "memory");
    asm volatile("red.global.add.v4.f32 [%0], {%1,%2,%3,%4};"
                 :: "l"(a + 4), "f"(r[4]), "f"(r[5]), "f"(r[6]), "f"(r[7]) : "memory");
}
__device__ __forceinline__ unsigned lanemask_le() {
    unsigned m; asm("mov.u32 %0, %%lanemask_le;" : "=r"(m)); return m;
}

// 32-slot segmented warp reduction keyed by dst (conv3)
__device__ __forceinline__ void segreduce_flush(float m[8], int dst, int lane, bool valid) {
    unsigned long long p[4];
    #pragma unroll
    for (int i = 0; i < 4; i++) p[i] = PACK2(m[2 * i], m[2 * i + 1]);
    #pragma unroll
    for (int off = 1; off < 32; off <<= 1) {
        int d2 = __shfl_up_sync(0xffffffffu, dst, off);
        bool take = (lane >= off) && (d2 == dst);
        #pragma unroll
        for (int i = 0; i < 4; i++) {
            unsigned long long t = __shfl_up_sync(0xffffffffu, p[i], off);
            if (take) p[i] = ADDX2(p[i], t);
        }
    }
    int dn = __shfl_down_sync(0xffffffffu, dst, 1);
    if (valid && (lane == 31 || dn != dst)) {
        float r[8];
        UNPACK2(p[0], r[0], r[1]); UNPACK2(p[1], r[2], r[3]);
        UNPACK2(p[2], r[4], r[5]); UNPACK2(p[3], r[6], r[7]);
        flush8(dst, r);
    }
}

// paired (2 slots/lane) segmented reduction: lane owns consecutive slots
// (2L, 2L+1) with messages mA/mB and keys dstA/dstB (-1 = invalid)
__device__ __forceinline__ void pair_reduce_flush(
    const float mA[8], const float mB[8], int dstA, int dstB, int lane)
{
    int prevB = __shfl_up_sync(0xffffffffu, dstB, 1);
    bool start = (lane == 0) || (dstA != dstB) || (prevB != dstA);
    unsigned startmask = __ballot_sync(0xffffffffu, start);
    int segid = __popc(startmask & lanemask_le());

    if (dstA != dstB && dstA >= 0) flush8(dstA, mA);   // mid-lane segment close

    unsigned long long p[4];
    bool same = (dstA == dstB);
    #pragma unroll
    for (int i = 0; i < 4; i++) {
        unsigned long long b_ = PACK2(mB[2 * i], mB[2 * i + 1]);
        p[i] = same ? ADDX2(PACK2(mA[2 * i], mA[2 * i + 1]), b_) : b_;
    }
    #pragma unroll
    for (int off = 1; off < 32; off <<= 1) {
        int s2 = __shfl_up_sync(0xffffffffu, segid, off);
        bool take = (lane >= off) && (s2 == segid);
        #pragma unroll
        for (int i = 0; i < 4; i++) {
            unsigned long long t = __shfl_up_sync(0xffffffffu, p[i], off);
            if (take) p[i] = ADDX2(p[i], t);
        }
    }
    bool end = (lane == 31) || ((startmask >> (lane + 1)) & 1u);
    if (end && dstB >= 0) {
        float r[8];
        UNPACK2(p[0], r[0], r[1]); UNPACK2(p[1], r[2], r[3]);
        UNPACK2(p[2], r[4], r[5]); UNPACK2(p[3], r[6], r[7]);
        flush8(dstB, r);
    }
}

// ---------------- CSR build ----------------

__global__ void count_kernel(const int4* __restrict__ dst4) {
    int e = blockIdx.x * blockDim.x + threadIdx.x;
    if (e < N_EDGES / 4) {
        int4 d = __ldg(&dst4[e]);
        atomicAdd(&g_deg[d.x], 1);
        atomicAdd(&g_deg[d.y], 1);
        atomicAdd(&g_deg[d.z], 1);
        atomicAdd(&g_deg[d.w], 1);
    }
}

__global__ void scan1_kernel() {
    __shared__ int sh[SCAN_BLOCK];
    int i = blockIdx.x * SCAN_BLOCK + threadIdx.x;
    int v = 0;
    if (i < N_NODES) {
        v = g_deg[i] + 1;                 // +1 self loop
        g_dinv[i] = rsqrtf((float)v);
        g_deg[i] = 0;                     // restore entry invariant
    }
    sh[threadIdx.x] = v;
    __syncthreads();
    #pragma unroll
    for (int o = 1; o < SCAN_BLOCK; o <<= 1) {
        int t = 0;
        if ((int)threadIdx.x >= o) t = sh[threadIdx.x - o];
        __syncthreads();
        sh[threadIdx.x] += t;
        __syncthreads();
    }
    if (i < N_NODES) g_off[i] = sh[threadIdx.x] - v;
    if (threadIdx.x == SCAN_BLOCK - 1) g_bsum[blockIdx.x] = sh[SCAN_BLOCK - 1];
}

// block-prefix fixup (inline bsum scan) + self-loop CSR + cursor + MLP + y
__global__ void scan3_fill_mlp_kernel(const float* __restrict__ x,
                                      const int* __restrict__ node_index,
                                      const float* __restrict__ emb,
                                      const float* __restrict__ W1,
                                      const float* __restrict__ b1,
                                      const float* __restrict__ Wv1,
                                      const float* __restrict__ Bv1) {
    __shared__ float sW[24 * 8 + 8];
    __shared__ int sPre;
    int t = threadIdx.x;
    if (t < 192) sW[t] = W1[t];
    else if (t < 200) sW[t] = b1[t - 192];
    if (t < 32) {                       // warp 0: prefix of bsum[0..bid)
        int s = 0;
        for (int j = t; j < SCAN_NBLK; j += 32)
            if (j < (int)blockIdx.x) s += g_bsum[j];
        #pragma unroll
        for (int o = 16; o; o >>= 1) s += __shfl_xor_sync(0xffffffffu, s, o);
        if (t == 0) sPre = s;
    }
    __syncthreads();

    int i = blockIdx.x * SCAN_BLOCK + t;
    if (i == 0) g_off[N_NODES] = TOT_SLOTS;
    if (i >= N_NODES) return;

    int off = g_off[i] + sPre;
    g_off[i] = off;
    float di = g_dinv[i];
    g_csr[off] = make_int4(i, __float_as_int(di), i, 0);   // w = dinv[src] only
    g_cursor[i] = off + 1;

    float in[24];
    int idx = node_index[i];
    #pragma unroll
    for (int j = 0; j < 8; j++) in[j] = emb[(size_t)idx * 8 + j];
    #pragma unroll
    for (int j = 0; j < 16; j++) in[8 + j] = x[(size_t)i * 16 + j];
    float o[8], y[8];
    #pragma unroll
    for (int c = 0; c < 8; c++) {
        float s = sW[192 + c];
        #pragma unroll
        for (int j = 0; j < 24; j++) s = fmaf(in[j], sW[j * 8 + c], s);
        o[c] = fmaxf(s, 0.0f);
        y[c] = di * fmaf(__ldg(Wv1 + c), o[c], __ldg(Bv1 + c));
    }
    g_x0[(size_t)i * 2]     = make_float4(o[0], o[1], o[2], o[3]);
    g_x0[(size_t)i * 2 + 1] = make_float4(o[4], o[5], o[6], o[7]);
    g_y[(size_t)i * 2]      = make_float4(y[0], y[1], y[2], y[3]);
    g_y[(size_t)i * 2 + 1]  = make_float4(y[4], y[5], y[6], y[7]);
}

__global__ void fill_edges_kernel(const int* __restrict__ src, const int* __restrict__ dst) {
    int e = blockIdx.x * blockDim.x + threadIdx.x;
    if (e < N_EDGES) {
        int s = src[e];
        int d = dst[e];
        float w = g_dinv[s];              // dinv[dst] applied in epilogue
        int p = atomicAdd(&g_cursor[d], 1);
        g_csr[p] = make_int4(s, __float_as_int(w), d, 0);
    }
}

// ---------------- conv1: paired SpMV of y ----------------------------------

__global__ void __launch_bounds__(256) econv1_kernel() {
    constexpr int S = 12;
    __shared__ float sx[8 * 64 * S];
    int warp = threadIdx.x >> 5, lane = threadIdx.x & 31;
    int base = (blockIdx.x * 8 + warp) * 64;
    if (base >= TOT_SLOTS) return;
    float* ws = sx + warp * (64 * S);

    int cnt = min(64, TOT_SLOTS - base);
    int4 eA = make_int4(0, 0, -1, 0), eB = make_int4(0, 0, -1, 0);
    if (2 * lane     < cnt) eA = __ldg(&g_csr[base + 2 * lane]);
    if (2 * lane + 1 < cnt) eB = __ldg(&g_csr[base + 2 * lane + 1]);

    int T = cnt * 2;
    #pragma unroll
    for (int r = 0; r < 4; r++) {
        int idx = r * 32 + lane;
        int ci = min(idx, T - 1);
        int e = ci >> 1, c = ci & 1;
        int sA = __shfl_sync(0xffffffffu, eA.x, e >> 1);
        int sB = __shfl_sync(0xffffffffu, eB.x, e >> 1);
        int s = (e & 1) ? sB : sA;
        if (idx < T) {
            int ms = (e >> 1) + ((e & 1) << 5);
            *(float4*)(ws + ms * S + c * 4) = __ldg(g_y + (size_t)s * 2 + c);
        }
    }
    __syncwarp();

    float mA[8] = {0,0,0,0,0,0,0,0}, mB[8] = {0,0,0,0,0,0,0,0};
    if (eA.z >= 0) {
        const float* xe = ws + lane * S;
        #pragma unroll
        for (int c = 0; c < 8; c++) mA[c] = xe[c];
    }
    if (eB.z >= 0) {
        const float* xe = ws + (lane + 32) * S;
        #pragma unroll
        for (int c = 0; c < 8; c++) mB[c] = xe[c];
    }
    pair_reduce_flush(mA, mB, eA.z, eB.z, lane);
}

// ---------------- conv2: paired 2-level attention via sigmoid --------------

__device__ __forceinline__ void conv2_msg(const float* xe, const float4& q0, const float4& q1,
                                          float w, const float* Wv, const float* Bv, float m[8]) {
    float x1[8], d01[8];
    #pragma unroll
    for (int c = 0; c < 8; c++) { x1[c] = xe[c]; d01[c] = xe[8 + c]; }
    float qk[8] = {q0.x, q0.y, q0.z, q0.w, q1.x, q1.y, q1.z, q1.w};
    float a[2];
    #pragma unroll
    for (int h = 0; h < 2; h++) {
        float s_ = 0.0f;
        #pragma unroll
        for (int d = 0; d < 4; d++) s_ = fmaf(qk[h * 4 + d], d01[h * 4 + d], s_);
        a[h] = 1.0f / (1.0f + __expf(-s_));
    }
    #pragma unroll
    for (int c = 0; c < 8; c++) {
        float t = fmaf(a[c >> 2], d01[c], x1[c]);
        m[c] = w * fmaf(__ldg(Wv + c), t, __ldg(Bv + c));
    }
}

__global__ void __launch_bounds__(256) econv2_kernel(
    const float* __restrict__ Wv, const float* __restrict__ Bv)
{
    constexpr int S = 20;
    __shared__ float sx[8 * 64 * S];
    int warp = threadIdx.x >> 5, lane = threadIdx.x & 31;
    int base = (blockIdx.x * 8 + warp) * 64;
    if (base >= TOT_SLOTS) return;
    float* ws = sx + warp * (64 * S);

    int cnt = min(64, TOT_SLOTS - base);
    int4 eA = make_int4(0, 0, -1, 0), eB = make_int4(0, 0, -1, 0);
    if (2 * lane     < cnt) eA = __ldg(&g_csr[base + 2 * lane]);
    if (2 * lane + 1 < cnt) eB = __ldg(&g_csr[base + 2 * lane + 1]);

    int T = cnt * 4;
    #pragma unroll
    for (int r = 0; r < 8; r++) {
        int idx = r * 32 + lane;
        int ci = min(idx, T - 1);
        int e = ci >> 2, c = ci & 3;
        int sA = __shfl_sync(0xffffffffu, eA.x, e >> 1);
        int sB = __shfl_sync(0xffffffffu, eB.x, e >> 1);
        int s = (e & 1) ? sB : sA;
        if (idx < T) {
            int ms = (e >> 1) + ((e & 1) << 5);
            *(float4*)(ws + ms * S + c * 4) = __ldg(g_r2 + (size_t)s * 4 + c);
        }
    }
    __syncwarp();

    float mA[8] = {0,0,0,0,0,0,0,0}, mB[8] = {0,0,0,0,0,0,0,0};
    if (eA.z >= 0) {
        float4 q0 = __ldg(g_q + (size_t)eA.z * 2);
        float4 q1 = __ldg(g_q + (size_t)eA.z * 2 + 1);
        conv2_msg(ws + lane * S, q0, q1, __int_as_float(eA.y), Wv, Bv, mA);
    }
    if (eB.z >= 0) {
        float4 q0 = __ldg(g_q + (size_t)eB.z * 2);
        float4 q1 = __ldg(g_q + (size_t)eB.z * 2 + 1);
        conv2_msg(ws + (lane + 32) * S, q0, q1, __int_as_float(eB.y), Wv, Bv, mB);
    }
    pair_reduce_flush(mA, mB, eA.z, eB.z, lane);
}

// ---------------- conv3: 3-level attention (32-slot form) ------------------

__global__ void __launch_bounds__(256) econv3_kernel(
    const float* __restrict__ Wv, const float* __restrict__ Bv)
{
    constexpr int S = 28;
    __shared__ float sx[8 * 32 * S];
    int warp = threadIdx.x >> 5, lane = threadIdx.x & 31;
    int base = (blockIdx.x * 8 + warp) * 32;
    if (base >= TOT_SLOTS) return;
    float* ws = sx + warp * (32 * S);

    int cnt = min(32, TOT_SLOTS - base);
    bool valid = lane < cnt;
    int4 ent = make_int4(0, 0, -1, 0);
    if (valid) ent = __ldg(&g_csr[base + lane]);
    int dst = ent.z;

    int T = cnt * 6;
    #pragma unroll
    for (int r = 0; r < 6; r++) {
        int idx = r * 32 + lane;
        int ci = min(idx, T - 1);
        int e = ci / 6, c = ci - e * 6;
        int s = __shfl_sync(0xffffffffu, ent.x, e);
        if (idx < T)
            *(float4*)(ws + e * S + c * 4) = __ldg(g_r3 + (size_t)s * 8 + c);
    }
    __syncwarp();

    float m[8] = {0.f, 0.f, 0.f, 0.f, 0.f, 0.f, 0.f, 0.f};
    if (valid) {
        float w = __int_as_float(ent.y);
        const float* xe = ws + lane * S;
        float x2[8], d02[8], d12[8];
        #pragma unroll
        for (int c = 0; c < 8; c++) {
            x2[c] = xe[c]; d02[c] = xe[8 + c]; d12[c] = xe[16 + c];
        }
        float4 q0 = __ldg(g_q + (size_t)dst * 2);
        float4 q1 = __ldg(g_q + (size_t)dst * 2 + 1);
        float qk[8] = {q0.x, q0.y, q0.z, q0.w, q1.x, q1.y, q1.z, q1.w};
        float a0[2], a1[2];
        #pragma unroll
        for (int h = 0; h < 2; h++) {
            float t0 = 0.0f, t1 = 0.0f;
            #pragma unroll
            for (int d = 0; d < 4; d++) {
                t0 = fmaf(qk[h * 4 + d], d02[h * 4 + d], t0);
                t1 = fmaf(qk[h * 4 + d], d12[h * 4 + d], t1);
            }
            float mx = fmaxf(fmaxf(t0, t1), 0.0f);
            float e0 = __expf(t0 - mx), e1 = __expf(t1 - mx), e2 = __expf(-mx);
            float inv = 1.0f / (e0 + e1 + e2);
            a0[h] = e0 * inv; a1[h] = e1 * inv;
        }
        #pragma unroll
        for (int c = 0; c < 8; c++) {
            int h = c >> 2;
            float t = fmaf(a0[h], d02[c], fmaf(a1[h], d12[c], x2[c]));
            m[c] = w * fmaf(__ldg(Wv + c), t, __ldg(Bv + c));
        }
    }
    segreduce_flush(m, dst, lane, valid);
}

// ---------------- epilogues (all scale by dinv[n]) ----------------

__global__ void epi1_kernel(const float* __restrict__ Wq2, const float* __restrict__ Bq2,
                            const float* __restrict__ Wk2) {
    int n = blockIdx.x * blockDim.x + threadIdx.x;
    if (n >= N_NODES) return;
    float4 a = g_acc[(size_t)n * 2];
    float4 b = g_acc[(size_t)n * 2 + 1];
    float4 z4 = make_float4(0.f, 0.f, 0.f, 0.f);
    g_acc[(size_t)n * 2] = z4;
    g_acc[(size_t)n * 2 + 1] = z4;
    float di = g_dinv[n];
    float x1[8] = {fmaxf(di * a.x, 0.f), fmaxf(di * a.y, 0.f), fmaxf(di * a.z, 0.f), fmaxf(di * a.w, 0.f),
                   fmaxf(di * b.x, 0.f), fmaxf(di * b.y, 0.f), fmaxf(di * b.z, 0.f), fmaxf(di * b.w, 0.f)};
    float4 xa = g_x0[(size_t)n * 2];
    float4 xb = g_x0[(size_t)n * 2 + 1];
    float x0[8] = {xa.x, xa.y, xa.z, xa.w, xb.x, xb.y, xb.z, xb.w};
    g_r2[(size_t)n * 4]     = make_float4(x1[0], x1[1], x1[2], x1[3]);
    g_r2[(size_t)n * 4 + 1] = make_float4(x1[4], x1[5], x1[6], x1[7]);
    g_r2[(size_t)n * 4 + 2] = make_float4(x0[0] - x1[0], x0[1] - x1[1], x0[2] - x1[2], x0[3] - x1[3]);
    g_r2[(size_t)n * 4 + 3] = make_float4(x0[4] - x1[4], x0[5] - x1[5], x0[6] - x1[6], x0[7] - x1[7]);
    float qk[8];
    #pragma unroll
    for (int c = 0; c < 8; c++) {
        float q = fmaf(x1[c], __ldg(Wq2 + c), __ldg(Bq2 + c));
        qk[c] = 0.5f * q * __ldg(Wk2 + c);
    }
    g_q[(size_t)n * 2]     = make_float4(qk[0], qk[1], qk[2], qk[3]);
    g_q[(size_t)n * 2 + 1] = make_float4(qk[4], qk[5], qk[6], qk[7]);
}

__global__ void epi2_kernel(const float* __restrict__ Wq3, const float* __restrict__ Bq3,
                            const float* __restrict__ Wk3) {
    int n = blockIdx.x * blockDim.x + threadIdx.x;
    if (n >= N_NODES) return;
    float4 a = g_acc[(size_t)n * 2];
    float4 b = g_acc[(size_t)n * 2 + 1];
    float4 z4 = make_float4(0.f, 0.f, 0.f, 0.f);
    g_acc[(size_t)n * 2] = z4;
    g_acc[(size_t)n * 2 + 1] = z4;
    float di = g_dinv[n];
    float x2[8] = {fmaxf(di * a.x, 0.f), fmaxf(di * a.y, 0.f), fmaxf(di * a.z, 0.f), fmaxf(di * a.w, 0.f),
                   fmaxf(di * b.x, 0.f), fmaxf(di * b.y, 0.f), fmaxf(di * b.z, 0.f), fmaxf(di * b.w, 0.f)};
    float4 r0 = g_r2[(size_t)n * 4];
    float4 r1 = g_r2[(size_t)n * 4 + 1];
    float4 r2 = g_r2[(size_t)n * 4 + 2];
    float4 r3 = g_r2[(size_t)n * 4 + 3];
    float x1[8] = {r0.x, r0.y, r0.z, r0.w, r1.x, r1.y, r1.z, r1.w};
    float x0[8] = {r0.x + r2.x, r0.y + r2.y, r0.z + r2.z, r0.w + r2.w,
                   r1.x + r3.x, r1.y + r3.y, r1.z + r3.z, r1.w + r3.w};
    g_r3[(size_t)n * 8]     = make_float4(x2[0], x2[1], x2[2], x2[3]);
    g_r3[(size_t)n * 8 + 1] = make_float4(x2[4], x2[5], x2[6], x2[7]);
    g_r3[(size_t)n * 8 + 2] = make_float4(x0[0] - x2[0], x0[1] - x2[1], x0[2] - x2[2], x0[3] - x2[3]);
    g_r3[(size_t)n * 8 + 3] = make_float4(x0[4] - x2[4], x0[5] - x2[5], x0[6] - x2[6], x0[7] - x2[7]);
    g_r3[(size_t)n * 8 + 4] = make_float4(x1[0] - x2[0], x1[1] - x2[1], x1[2] - x2[2], x1[3] - x2[3]);
    g_r3[(size_t)n * 8 + 5] = make_float4(x1[4] - x2[4], x1[5] - x2[5], x1[6] - x2[6], x1[7] - x2[7]);
    float qk[8];
    #pragma unroll
    for (int c = 0; c < 8; c++) {
        float q = fmaf(x2[c], __ldg(Wq3 + c), __ldg(Bq3 + c));
        qk[c] = 0.5f * q * __ldg(Wk3 + c);
    }
    g_q[(size_t)n * 2]     = make_float4(qk[0], qk[1], qk[2], qk[3]);
    g_q[(size_t)n * 2 + 1] = make_float4(qk[4], qk[5], qk[6], qk[7]);
}

__global__ void epi3_kernel(const float* __restrict__ W2, const float* __restrict__ b2,
                            float* __restrict__ out) {
    int n = blockIdx.x * blockDim.x + threadIdx.x;
    if (n >= N_NODES) return;
    float4 a = g_acc[(size_t)n * 2];
    float4 b = g_acc[(size_t)n * 2 + 1];
    float4 z4 = make_float4(0.f, 0.f, 0.f, 0.f);
    g_acc[(size_t)n * 2] = z4;
    g_acc[(size_t)n * 2 + 1] = z4;
    float di = g_dinv[n];
    float xl[8] = {fmaxf(di * a.x, 0.f), fmaxf(di * a.y, 0.f), fmaxf(di * a.z, 0.f), fmaxf(di * a.w, 0.f),
                   fmaxf(di * b.x, 0.f), fmaxf(di * b.y, 0.f), fmaxf(di * b.z, 0.f), fmaxf(di * b.w, 0.f)};
    float z0 = __ldg(b2 + 0), z1 = __ldg(b2 + 1);
    #pragma unroll
    for (int c = 0; c < 8; c++) {
        z0 = fmaf(xl[c], __ldg(W2 + c * 2 + 0), z0);
        z1 = fmaf(xl[c], __ldg(W2 + c * 2 + 1), z1);
    }
    float mx = fmaxf(z0, z1);
    float lse = mx + __logf(__expf(z0 - mx) + __expf(z1 - mx));
    out[(size_t)n * 2 + 0] = z0 - lse;
    out[(size_t)n * 2 + 1] = z1 - lse;
}

// ---------------- launch ----------------

extern "C" void kernel_launch(void* const* d_in, const int* in_sizes, int n_in,
                              void* d_out, int out_size) {
    const float* x    = (const float*)d_in[0];
    const int*   nidx = (const int*)  d_in[1];
    const int*   eidx = (const int*)  d_in[3];   // [2, E]
    const float* emb  = (const float*)d_in[5];
    const float* W1   = (const float*)d_in[6];
    const float* b1   = (const float*)d_in[7];
    const float* Wq   = (const float*)d_in[8];
    const float* bq   = (const float*)d_in[9];
    const float* Wk   = (const float*)d_in[10];
    const float* Wv   = (const float*)d_in[12];
    const float* bv   = (const float*)d_in[13];
    const float* W2   = (const float*)d_in[14];
    const float* b2   = (const float*)d_in[15];
    float* out = (float*)d_out;

    const int* src = eidx;
    const int* dst = eidx + N_EDGES;

    int nb_n  = (N_NODES + 255) / 256;
    int nb_e  = (N_EDGES + 255) / 256;
    int nb_e4 = (N_EDGES / 4 + 255) / 256;
    int nb_c  = (TOT_SLOTS + 255) / 256;          // 32 slots/warp (conv3)
    int nb_p  = (TOT_SLOTS + 511) / 512;          // 64 slots/warp (conv1/2)

    count_kernel<<<nb_e4, 256>>>((const int4*)dst);
    scan1_kernel<<<SCAN_NBLK, SCAN_BLOCK>>>();
    scan3_fill_mlp_kernel<<<SCAN_NBLK, SCAN_BLOCK>>>(x, nidx, emb, W1, b1, Wv + 0, bv + 0);
    fill_edges_kernel<<<nb_e, 256>>>(src, dst);

    econv1_kernel<<<nb_p, 256>>>();
    epi1_kernel<<<nb_n, 256>>>(Wq + 8, bq + 8, Wk + 8);
    econv2_kernel<<<nb_p, 256>>>(Wv + 8, bv + 8);
    epi2_kernel<<<nb_n, 256>>>(Wq + 16, bq + 16, Wk + 16);
    econv3_kernel<<<nb_c, 256>>>(Wv + 16, bv + 16);
    epi3_kernel<<<nb_n, 256>>>(W2, b2, out);
}